// round 2
// baseline (speedup 1.0000x reference)
#include <cuda_runtime.h>
#include <cuda_bf16.h>
#include <math.h>

#define V_NODES 10000
#define DEG 32
#define NB 16
#define KORD 6
#define E_EDGES (V_NODES * DEG)

// 6 big rotating buffers of (V, 128*16) floats + bn stats + pool partials
#define BUFSZ (V_NODES * 2048)
__device__ float g_buf[6 * BUFSZ + 4 * 256 + 25 * 2048];

// ---------------------------------------------------------------------------
// transpose input x (B,8,V) -> (V, c*16+b)
// ---------------------------------------------------------------------------
__global__ void transpose_x_kernel(float* __restrict__ out, const float* __restrict__ x) {
    int i = blockIdx.x * 256 + threadIdx.x;
    if (i >= V_NODES * 128) return;
    int b = i & 15;
    int c = (i >> 4) & 7;
    int v = i >> 7;
    out[i] = x[(b * 8 + c) * V_NODES + v];
}

// ---------------------------------------------------------------------------
// SpMM: y[v,f] = sum_e vals[v*32+e] * z[col[v*32+e], f]
// FUSED: y = 2*spmm - prev
// One block per node. blockDim = min(256, F/4).
// ---------------------------------------------------------------------------
template<int F, bool FUSED>
__global__ void __launch_bounds__(256) spmm_kernel(
    float* __restrict__ y, const float* __restrict__ z, const float* __restrict__ prev,
    const int* __restrict__ col, const float* __restrict__ vals)
{
    constexpr int F4 = F / 4;
    int v = blockIdx.x;
    __shared__ int scol[DEG];
    __shared__ float sval[DEG];
    int t = threadIdx.x;
    if (t < DEG) {
        scol[t] = col[v * DEG + t];
        sval[t] = vals[v * DEG + t];
    }
    __syncthreads();

    const float4* z4 = (const float4*)z;
    const float4* p4 = (const float4*)prev;
    float4* y4 = (float4*)y;

    for (int f = t; f < F4; f += blockDim.x) {
        float4 acc = make_float4(0.f, 0.f, 0.f, 0.f);
#pragma unroll 8
        for (int e = 0; e < DEG; e++) {
            float w = sval[e];
            float4 zz = z4[scol[e] * F4 + f];
            acc.x = fmaf(w, zz.x, acc.x);
            acc.y = fmaf(w, zz.y, acc.y);
            acc.z = fmaf(w, zz.z, acc.z);
            acc.w = fmaf(w, zz.w, acc.w);
        }
        if (FUSED) {
            float4 p = p4[v * F4 + f];
            acc.x = 2.f * acc.x - p.x;
            acc.y = 2.f * acc.y - p.y;
            acc.z = 2.f * acc.z - p.z;
            acc.w = 2.f * acc.w - p.w;
        }
        y4[v * F4 + f] = acc;
    }
}

// ---------------------------------------------------------------------------
// Cheb term GEMM: out[v, o*16+b] (+)= sum_c T[v, c*16+b] * W[c, o]
// INIT: out = bias[o] + term ; else out += term
// 4 nodes per block, 256 threads: thread = (b = tid&15, og = tid>>4),
// covers o = og + 16*j for j < COUT/16.
// ---------------------------------------------------------------------------
template<int CIN, int COUT, bool INIT>
__global__ void __launch_bounds__(256) chebgemm_kernel(
    float* __restrict__ out, const float* __restrict__ T,
    const float* __restrict__ W, const float* __restrict__ bias)
{
    constexpr int NV = 4;
    constexpr int CK = (CIN < 16) ? CIN : 16;
    constexpr int OG = COUT / 16;
    __shared__ float Ts[NV * CIN * 16];
    __shared__ float Ws[CK * COUT];

    int tid = threadIdx.x;
    int b = tid & 15;
    int og = tid >> 4;
    int v0 = blockIdx.x * NV;

    const float* Tg = T + (size_t)v0 * CIN * 16;
    for (int i = tid; i < NV * CIN * 16; i += 256) Ts[i] = Tg[i];

    float acc[NV][OG];
#pragma unroll
    for (int n = 0; n < NV; n++)
#pragma unroll
        for (int j = 0; j < OG; j++)
            acc[n][j] = INIT ? bias[og + 16 * j] : 0.f;

    for (int c0 = 0; c0 < CIN; c0 += CK) {
        __syncthreads();
        for (int i = tid; i < CK * COUT; i += 256) Ws[i] = W[c0 * COUT + i];
        __syncthreads();
#pragma unroll
        for (int cc = 0; cc < CK; cc++) {
            float tv[NV];
#pragma unroll
            for (int n = 0; n < NV; n++) tv[n] = Ts[n * CIN * 16 + (c0 + cc) * 16 + b];
#pragma unroll
            for (int j = 0; j < OG; j++) {
                float wv = Ws[cc * COUT + og + 16 * j];
#pragma unroll
                for (int n = 0; n < NV; n++) acc[n][j] = fmaf(tv[n], wv, acc[n][j]);
            }
        }
    }

#pragma unroll
    for (int n = 0; n < NV; n++)
#pragma unroll
        for (int j = 0; j < OG; j++) {
            size_t idx = (size_t)(v0 + n) * COUT * 16 + (og + 16 * j) * 16 + b;
            if (INIT) out[idx] = acc[n][j];
            else      out[idx] += acc[n][j];
        }
}

// ---------------------------------------------------------------------------
// BatchNorm stats (training mode) over (B,V) per channel, with relu-on-read.
// One block per channel. ss[2c]=scale, ss[2c+1]=shift.
// ---------------------------------------------------------------------------
__global__ void __launch_bounds__(256) bnstats_kernel(
    const float* __restrict__ h, const float* __restrict__ g,
    const float* __restrict__ be, float* __restrict__ ss, int C)
{
    int c = blockIdx.x;
    int F = C * 16;
    float s1 = 0.f, s2 = 0.f;
    for (int k = threadIdx.x; k < V_NODES * 16; k += 256) {
        int v = k >> 4, b = k & 15;
        float x = h[(size_t)v * F + c * 16 + b];
        x = fmaxf(x, 0.f);
        s1 += x;
        s2 += x * x;
    }
    __shared__ float r1[256], r2[256];
    r1[threadIdx.x] = s1; r2[threadIdx.x] = s2;
    __syncthreads();
    for (int s = 128; s > 0; s >>= 1) {
        if (threadIdx.x < s) {
            r1[threadIdx.x] += r1[threadIdx.x + s];
            r2[threadIdx.x] += r2[threadIdx.x + s];
        }
        __syncthreads();
    }
    if (threadIdx.x == 0) {
        float n = (float)(V_NODES * 16);
        float m = r1[0] / n;
        float var = r2[0] / n - m * m;
        float rstd = rsqrtf(var + 1e-5f);
        float sc = g[c] * rstd;
        ss[2 * c] = sc;
        ss[2 * c + 1] = be[c] - m * sc;
    }
}

__global__ void __launch_bounds__(256) bnapply_kernel(
    float4* __restrict__ out, const float4* __restrict__ in,
    const float* __restrict__ ss, int C, int n4)
{
    int i = blockIdx.x * 256 + threadIdx.x;
    if (i >= n4) return;
    int c = (i >> 2) % C;
    float sc = ss[2 * c], sh = ss[2 * c + 1];
    float4 v = in[i];
    v.x = fmaxf(v.x, 0.f) * sc + sh;
    v.y = fmaxf(v.y, 0.f) * sc + sh;
    v.z = fmaxf(v.z, 0.f) * sc + sh;
    v.w = fmaxf(v.w, 0.f) * sc + sh;
    out[i] = v;
}

// ---------------------------------------------------------------------------
// Max-pool over V, stage 1: 25 row-chunks of 400, G=2048 columns
// ---------------------------------------------------------------------------
__global__ void pool1_kernel(float* __restrict__ pp, const float* __restrict__ h) {
    int col = blockIdx.x * 256 + threadIdx.x;
    int ch = blockIdx.y;
    int v0 = ch * 400;
    float m = -INFINITY;
    for (int v = v0; v < v0 + 400; v++) m = fmaxf(m, h[(size_t)v * 2048 + col]);
    pp[ch * 2048 + col] = m;
}

// ---------------------------------------------------------------------------
// Head: final pool reduce + relu, BN over batch, linear 128->10, relu, log_softmax
// ---------------------------------------------------------------------------
__global__ void __launch_bounds__(256) head_kernel(
    float* __restrict__ out, const float* __restrict__ pp,
    const float* __restrict__ g, const float* __restrict__ be,
    const float* __restrict__ lw, const float* __restrict__ lb)
{
    __shared__ float pooled[2048];  // [c*16+b]
    __shared__ float xbn[2048];
    __shared__ float logits[160];
    __shared__ float rowred[16];
    int t = threadIdx.x;

    for (int col = t; col < 2048; col += 256) {
        float m = -INFINITY;
        for (int ch = 0; ch < 25; ch++) m = fmaxf(m, pp[ch * 2048 + col]);
        pooled[col] = fmaxf(m, 0.f);  // relu(max) == max(relu)
    }
    __syncthreads();

    if (t < 128) {
        float s1 = 0.f, s2 = 0.f;
        for (int b = 0; b < 16; b++) {
            float x = pooled[t * 16 + b];
            s1 += x; s2 += x * x;
        }
        float m = s1 / 16.f;
        float var = s2 / 16.f - m * m;
        float sc = g[t] * rsqrtf(var + 1e-5f);
        float sh = be[t] - m * sc;
        for (int b = 0; b < 16; b++) xbn[t * 16 + b] = pooled[t * 16 + b] * sc + sh;
    }
    __syncthreads();

    if (t < 160) {
        int b = t / 10, o = t % 10;
        float a = lb[o];
        for (int c = 0; c < 128; c++) a = fmaf(xbn[c * 16 + b], lw[c * 10 + o], a);
        logits[t] = fmaxf(a, 0.f);
    }
    __syncthreads();

    if (t < 16) {
        float m = -INFINITY;
        for (int o = 0; o < 10; o++) m = fmaxf(m, logits[t * 10 + o]);
        float s = 0.f;
        for (int o = 0; o < 10; o++) s += expf(logits[t * 10 + o] - m);
        rowred[t] = m + logf(s);
    }
    __syncthreads();

    if (t < 160) out[t] = logits[t] - rowred[t / 10];
}

// ---------------------------------------------------------------------------
// Host orchestration
// ---------------------------------------------------------------------------
extern "C" void kernel_launch(void* const* d_in, const int* in_sizes, int n_in,
                              void* d_out, int out_size) {
    const float* x      = (const float*)d_in[0];
    const float* w_in   = (const float*)d_in[1];
    const float* b_in   = (const float*)d_in[2];
    const float* g1     = (const float*)d_in[3];
    const float* be1    = (const float*)d_in[4];
    const float* w1a    = (const float*)d_in[5];
    const float* b1a    = (const float*)d_in[6];
    const float* g1h    = (const float*)d_in[7];
    const float* be1h   = (const float*)d_in[8];
    const float* w1b    = (const float*)d_in[9];
    const float* b1b    = (const float*)d_in[10];
    const float* sc1    = (const float*)d_in[11];
    const float* g2     = (const float*)d_in[12];
    const float* be2    = (const float*)d_in[13];
    const float* w2a    = (const float*)d_in[14];
    const float* b2a    = (const float*)d_in[15];
    const float* g2h    = (const float*)d_in[16];
    const float* be2h   = (const float*)d_in[17];
    const float* w2b    = (const float*)d_in[18];
    const float* b2b    = (const float*)d_in[19];
    const float* sc2    = (const float*)d_in[20];
    const float* g_out  = (const float*)d_in[21];
    const float* be_out = (const float*)d_in[22];
    const float* lin_w  = (const float*)d_in[23];
    const float* lin_b  = (const float*)d_in[24];
    const float* vals   = (const float*)d_in[25];
    const int*   lidx   = (const int*)d_in[26];
    const int*   col    = lidx + E_EDGES;  // lap_idx[1,:]

    float* base = nullptr;
    cudaGetSymbolAddress((void**)&base, g_buf);
    float* B0 = base;
    float* B1 = base + 1 * BUFSZ;
    float* B2 = base + 2 * BUFSZ;
    float* B3 = base + 3 * BUFSZ;
    float* B4 = base + 4 * BUFSZ;
    float* B5 = base + 5 * BUFSZ;
    float* st0 = base + 6 * BUFSZ;
    float* st1 = st0 + 256;
    float* st2 = st1 + 256;
    float* st3 = st2 + 256;
    float* pp  = st3 + 256;

    // ===== Layer 1: cheb(x, w_in, b_in), Cin=8 Cout=32 =====
    transpose_x_kernel<<<(V_NODES * 128 + 255) / 256, 256>>>(B0, x);
    chebgemm_kernel<8, 32, true><<<V_NODES / 4, 256>>>(B4, B0, w_in, b_in);
    spmm_kernel<128, false><<<V_NODES, 32>>>(B1, B0, nullptr, col, vals);
    chebgemm_kernel<8, 32, false><<<V_NODES / 4, 256>>>(B4, B1, w_in + 1 * 256, nullptr);
    spmm_kernel<128, true><<<V_NODES, 32>>>(B2, B1, B0, col, vals);
    chebgemm_kernel<8, 32, false><<<V_NODES / 4, 256>>>(B4, B2, w_in + 2 * 256, nullptr);
    spmm_kernel<128, true><<<V_NODES, 32>>>(B0, B2, B1, col, vals);
    chebgemm_kernel<8, 32, false><<<V_NODES / 4, 256>>>(B4, B0, w_in + 3 * 256, nullptr);
    spmm_kernel<128, true><<<V_NODES, 32>>>(B1, B0, B2, col, vals);
    chebgemm_kernel<8, 32, false><<<V_NODES / 4, 256>>>(B4, B1, w_in + 4 * 256, nullptr);
    spmm_kernel<128, true><<<V_NODES, 32>>>(B2, B1, B0, col, vals);
    chebgemm_kernel<8, 32, false><<<V_NODES / 4, 256>>>(B4, B2, w_in + 5 * 256, nullptr);
    // B4 = pre-relu h1 (C=32)

    // ===== Block 1: 32 -> 64 -> 64, shortcut 32->64 =====
    bnstats_kernel<<<32, 256>>>(B4, g1, be1, st0, 32);
    bnapply_kernel<<<(V_NODES * 32 * 4 + 255) / 256, 256>>>((float4*)B3, (const float4*)B4, st0, 32, V_NODES * 32 * 4);
    // chebA: B3 (32) -> B5 (64)
    chebgemm_kernel<32, 64, true><<<V_NODES / 4, 256>>>(B5, B3, w1a, b1a);
    spmm_kernel<512, false><<<V_NODES, 128>>>(B1, B3, nullptr, col, vals);
    chebgemm_kernel<32, 64, false><<<V_NODES / 4, 256>>>(B5, B1, w1a + 1 * 2048, nullptr);
    spmm_kernel<512, true><<<V_NODES, 128>>>(B2, B1, B3, col, vals);
    chebgemm_kernel<32, 64, false><<<V_NODES / 4, 256>>>(B5, B2, w1a + 2 * 2048, nullptr);
    spmm_kernel<512, true><<<V_NODES, 128>>>(B0, B2, B1, col, vals);
    chebgemm_kernel<32, 64, false><<<V_NODES / 4, 256>>>(B5, B0, w1a + 3 * 2048, nullptr);
    spmm_kernel<512, true><<<V_NODES, 128>>>(B1, B0, B2, col, vals);
    chebgemm_kernel<32, 64, false><<<V_NODES / 4, 256>>>(B5, B1, w1a + 4 * 2048, nullptr);
    spmm_kernel<512, true><<<V_NODES, 128>>>(B2, B1, B0, col, vals);
    chebgemm_kernel<32, 64, false><<<V_NODES / 4, 256>>>(B5, B2, w1a + 5 * 2048, nullptr);
    // mid bn: B5 (64) -> B0
    bnstats_kernel<<<64, 256>>>(B5, g1h, be1h, st1, 64);
    bnapply_kernel<<<(V_NODES * 64 * 4 + 255) / 256, 256>>>((float4*)B0, (const float4*)B5, st1, 64, V_NODES * 64 * 4);
    // chebB: B0 (64) -> B4 (64)
    chebgemm_kernel<64, 64, true><<<V_NODES / 4, 256>>>(B4, B0, w1b, b1b);
    spmm_kernel<1024, false><<<V_NODES, 256>>>(B1, B0, nullptr, col, vals);
    chebgemm_kernel<64, 64, false><<<V_NODES / 4, 256>>>(B4, B1, w1b + 1 * 4096, nullptr);
    spmm_kernel<1024, true><<<V_NODES, 256>>>(B2, B1, B0, col, vals);
    chebgemm_kernel<64, 64, false><<<V_NODES / 4, 256>>>(B4, B2, w1b + 2 * 4096, nullptr);
    spmm_kernel<1024, true><<<V_NODES, 256>>>(B5, B2, B1, col, vals);
    chebgemm_kernel<64, 64, false><<<V_NODES / 4, 256>>>(B4, B5, w1b + 3 * 4096, nullptr);
    spmm_kernel<1024, true><<<V_NODES, 256>>>(B1, B5, B2, col, vals);
    chebgemm_kernel<64, 64, false><<<V_NODES / 4, 256>>>(B4, B1, w1b + 4 * 4096, nullptr);
    spmm_kernel<1024, true><<<V_NODES, 256>>>(B2, B1, B5, col, vals);
    chebgemm_kernel<64, 64, false><<<V_NODES / 4, 256>>>(B4, B2, w1b + 5 * 4096, nullptr);
    // shortcut: B4 += B3 @ sc1
    chebgemm_kernel<32, 64, false><<<V_NODES / 4, 256>>>(B4, B3, sc1, nullptr);
    // B4 = pre-relu block1 out (C=64)

    // ===== Block 2: 64 -> 128 -> 128, shortcut 64->128 =====
    bnstats_kernel<<<64, 256>>>(B4, g2, be2, st2, 64);
    bnapply_kernel<<<(V_NODES * 64 * 4 + 255) / 256, 256>>>((float4*)B3, (const float4*)B4, st2, 64, V_NODES * 64 * 4);
    // chebA: B3 (64) -> B5 (128)
    chebgemm_kernel<64, 128, true><<<V_NODES / 4, 256>>>(B5, B3, w2a, b2a);
    spmm_kernel<1024, false><<<V_NODES, 256>>>(B1, B3, nullptr, col, vals);
    chebgemm_kernel<64, 128, false><<<V_NODES / 4, 256>>>(B5, B1, w2a + 1 * 8192, nullptr);
    spmm_kernel<1024, true><<<V_NODES, 256>>>(B2, B1, B3, col, vals);
    chebgemm_kernel<64, 128, false><<<V_NODES / 4, 256>>>(B5, B2, w2a + 2 * 8192, nullptr);
    spmm_kernel<1024, true><<<V_NODES, 256>>>(B0, B2, B1, col, vals);
    chebgemm_kernel<64, 128, false><<<V_NODES / 4, 256>>>(B5, B0, w2a + 3 * 8192, nullptr);
    spmm_kernel<1024, true><<<V_NODES, 256>>>(B1, B0, B2, col, vals);
    chebgemm_kernel<64, 128, false><<<V_NODES / 4, 256>>>(B5, B1, w2a + 4 * 8192, nullptr);
    spmm_kernel<1024, true><<<V_NODES, 256>>>(B2, B1, B0, col, vals);
    chebgemm_kernel<64, 128, false><<<V_NODES / 4, 256>>>(B5, B2, w2a + 5 * 8192, nullptr);
    // mid bn: B5 (128) -> B0
    bnstats_kernel<<<128, 256>>>(B5, g2h, be2h, st3, 128);
    bnapply_kernel<<<(V_NODES * 128 * 4 + 255) / 256, 256>>>((float4*)B0, (const float4*)B5, st3, 128, V_NODES * 128 * 4);
    // chebB: B0 (128) -> B4 (128)
    chebgemm_kernel<128, 128, true><<<V_NODES / 4, 256>>>(B4, B0, w2b, b2b);
    spmm_kernel<2048, false><<<V_NODES, 256>>>(B1, B0, nullptr, col, vals);
    chebgemm_kernel<128, 128, false><<<V_NODES / 4, 256>>>(B4, B1, w2b + 1 * 16384, nullptr);
    spmm_kernel<2048, true><<<V_NODES, 256>>>(B2, B1, B0, col, vals);
    chebgemm_kernel<128, 128, false><<<V_NODES / 4, 256>>>(B4, B2, w2b + 2 * 16384, nullptr);
    spmm_kernel<2048, true><<<V_NODES, 256>>>(B5, B2, B1, col, vals);
    chebgemm_kernel<128, 128, false><<<V_NODES / 4, 256>>>(B4, B5, w2b + 3 * 16384, nullptr);
    spmm_kernel<2048, true><<<V_NODES, 256>>>(B1, B5, B2, col, vals);
    chebgemm_kernel<128, 128, false><<<V_NODES / 4, 256>>>(B4, B1, w2b + 4 * 16384, nullptr);
    spmm_kernel<2048, true><<<V_NODES, 256>>>(B2, B1, B5, col, vals);
    chebgemm_kernel<128, 128, false><<<V_NODES / 4, 256>>>(B4, B2, w2b + 5 * 16384, nullptr);
    // shortcut: B4 += B3 @ sc2
    chebgemm_kernel<64, 128, false><<<V_NODES / 4, 256>>>(B4, B3, sc2, nullptr);
    // B4 = pre-relu final (C=128)

    // ===== Head =====
    pool1_kernel<<<dim3(8, 25), 256>>>(pp, B4);
    head_kernel<<<1, 256>>>((float*)d_out, pp, g_out, be_out, lin_w, lin_b);
}

// round 3
// speedup vs baseline: 1.0774x; 1.0774x over previous
#include <cuda_runtime.h>
#include <cuda_bf16.h>
#include <math.h>

#define V_NODES 10000
#define DEG 32
#define NB 16
#define KORD 6
#define E_EDGES (V_NODES * DEG)

// 6 big rotating buffers of (V, 128*16) floats + bn stats + pool partials
#define BUFSZ (V_NODES * 2048)
__device__ float g_buf[6 * BUFSZ + 4 * 256 + 25 * 2048];

// ---------------------------------------------------------------------------
// transpose input x (B,8,V) -> (V, c*16+b)
// ---------------------------------------------------------------------------
__global__ void transpose_x_kernel(float* __restrict__ out, const float* __restrict__ x) {
    int i = blockIdx.x * 256 + threadIdx.x;
    if (i >= V_NODES * 128) return;
    int b = i & 15;
    int c = (i >> 4) & 7;
    int v = i >> 7;
    out[i] = x[(b * 8 + c) * V_NODES + v];
}

// ---------------------------------------------------------------------------
// FUSED spmm + term-GEMM. One block per node v.
//   Phase 1 (L2-bound):  Tnew_row = L @ Tp1   (FIRST)  or  2*L@Tp1 - Tp2
//                        written to smem Ts AND gmem Tnew (recursion buffer)
//   Phase 2 (FMA-bound): out_row += Ts @ W    (W staged in smem)
// Thread map phase 2: bq = tid&3 covers b in [4bq,4bq+4) via float4,
//                     oq = tid>>2 covers o = oq + 64*j.
// ---------------------------------------------------------------------------
template<int CIN, int COUT, bool FIRST>
__global__ void __launch_bounds__(256) fused_spmm_gemm(
    float* __restrict__ Tnew, const float* __restrict__ Tp1, const float* __restrict__ Tp2,
    float* __restrict__ out, const float* __restrict__ W,
    const int* __restrict__ col, const float* __restrict__ vals)
{
    constexpr int F = CIN * 16;
    constexpr int F4 = F / 4;
    constexpr int J = (COUT + 63) / 64;

    extern __shared__ float sm[];
    float* Ts = sm;               // F floats
    float* Ws = sm + F;           // CIN*COUT floats
    __shared__ int scol[DEG];
    __shared__ float sval[DEG];

    int v = blockIdx.x;
    int t = threadIdx.x;
    if (t < DEG) {
        scol[t] = col[v * DEG + t];
        sval[t] = vals[v * DEG + t];
    }
    // stage W (same for every block; L2-resident)
    for (int i = t; i < CIN * COUT / 4; i += 256)
        ((float4*)Ws)[i] = ((const float4*)W)[i];
    __syncthreads();

    const float4* z4 = (const float4*)Tp1;
    const float4* p4 = (const float4*)Tp2;
    float4* y4 = (float4*)Tnew;

    for (int f = t; f < F4; f += 256) {
        float4 acc = make_float4(0.f, 0.f, 0.f, 0.f);
#pragma unroll 8
        for (int e = 0; e < DEG; e++) {
            float w = sval[e];
            float4 zz = z4[(size_t)scol[e] * F4 + f];
            acc.x = fmaf(w, zz.x, acc.x);
            acc.y = fmaf(w, zz.y, acc.y);
            acc.z = fmaf(w, zz.z, acc.z);
            acc.w = fmaf(w, zz.w, acc.w);
        }
        if (!FIRST) {
            float4 p = p4[(size_t)v * F4 + f];
            acc.x = 2.f * acc.x - p.x;
            acc.y = 2.f * acc.y - p.y;
            acc.z = 2.f * acc.z - p.z;
            acc.w = 2.f * acc.w - p.w;
        }
        ((float4*)Ts)[f] = acc;
        y4[(size_t)v * F4 + f] = acc;
    }
    __syncthreads();

    // phase 2
    int bq = t & 3;
    int oq = t >> 2;
    if (COUT < 64 && oq >= COUT) return;

    float4 acc[J];
#pragma unroll
    for (int j = 0; j < J; j++) acc[j] = make_float4(0.f, 0.f, 0.f, 0.f);

#pragma unroll 4
    for (int c = 0; c < CIN; c++) {
        float4 tv = *(const float4*)&Ts[c * 16 + 4 * bq];
#pragma unroll
        for (int j = 0; j < J; j++) {
            float wv = Ws[c * COUT + oq + 64 * j];
            acc[j].x = fmaf(tv.x, wv, acc[j].x);
            acc[j].y = fmaf(tv.y, wv, acc[j].y);
            acc[j].z = fmaf(tv.z, wv, acc[j].z);
            acc[j].w = fmaf(tv.w, wv, acc[j].w);
        }
    }
#pragma unroll
    for (int j = 0; j < J; j++) {
        int o = oq + 64 * j;
        float4* po = (float4*)&out[(size_t)v * COUT * 16 + o * 16 + 4 * bq];
        float4 cur = *po;
        cur.x += acc[j].x; cur.y += acc[j].y; cur.z += acc[j].z; cur.w += acc[j].w;
        *po = cur;
    }
}

// ---------------------------------------------------------------------------
// Cheb term GEMM (k=0 / shortcut): out[v,o*16+b] (+)= sum_c T[v,c*16+b]*W[c,o]
// ---------------------------------------------------------------------------
template<int CIN, int COUT, bool INIT>
__global__ void __launch_bounds__(256) chebgemm_kernel(
    float* __restrict__ out, const float* __restrict__ T,
    const float* __restrict__ W, const float* __restrict__ bias)
{
    constexpr int NV = 4;
    constexpr int CK = (CIN < 16) ? CIN : 16;
    constexpr int OG = COUT / 16;
    __shared__ float Ts[NV * CIN * 16];
    __shared__ float Ws[CK * COUT];

    int tid = threadIdx.x;
    int b = tid & 15;
    int og = tid >> 4;
    int v0 = blockIdx.x * NV;

    const float* Tg = T + (size_t)v0 * CIN * 16;
    for (int i = tid; i < NV * CIN * 16; i += 256) Ts[i] = Tg[i];

    float acc[NV][OG];
#pragma unroll
    for (int n = 0; n < NV; n++)
#pragma unroll
        for (int j = 0; j < OG; j++)
            acc[n][j] = INIT ? bias[og + 16 * j] : 0.f;

    for (int c0 = 0; c0 < CIN; c0 += CK) {
        __syncthreads();
        for (int i = tid; i < CK * COUT; i += 256) Ws[i] = W[c0 * COUT + i];
        __syncthreads();
#pragma unroll
        for (int cc = 0; cc < CK; cc++) {
            float tv[NV];
#pragma unroll
            for (int n = 0; n < NV; n++) tv[n] = Ts[n * CIN * 16 + (c0 + cc) * 16 + b];
#pragma unroll
            for (int j = 0; j < OG; j++) {
                float wv = Ws[cc * COUT + og + 16 * j];
#pragma unroll
                for (int n = 0; n < NV; n++) acc[n][j] = fmaf(tv[n], wv, acc[n][j]);
            }
        }
    }

#pragma unroll
    for (int n = 0; n < NV; n++)
#pragma unroll
        for (int j = 0; j < OG; j++) {
            size_t idx = (size_t)(v0 + n) * COUT * 16 + (og + 16 * j) * 16 + b;
            if (INIT) out[idx] = acc[n][j];
            else      out[idx] += acc[n][j];
        }
}

// ---------------------------------------------------------------------------
// BatchNorm stats (training mode) over (B,V) per channel, with relu-on-read.
// ---------------------------------------------------------------------------
__global__ void __launch_bounds__(256) bnstats_kernel(
    const float* __restrict__ h, const float* __restrict__ g,
    const float* __restrict__ be, float* __restrict__ ss, int C)
{
    int c = blockIdx.x;
    int F = C * 16;
    float s1 = 0.f, s2 = 0.f;
    for (int k = threadIdx.x; k < V_NODES * 16; k += 256) {
        int v = k >> 4, b = k & 15;
        float x = h[(size_t)v * F + c * 16 + b];
        x = fmaxf(x, 0.f);
        s1 += x;
        s2 += x * x;
    }
    __shared__ float r1[256], r2[256];
    r1[threadIdx.x] = s1; r2[threadIdx.x] = s2;
    __syncthreads();
    for (int s = 128; s > 0; s >>= 1) {
        if (threadIdx.x < s) {
            r1[threadIdx.x] += r1[threadIdx.x + s];
            r2[threadIdx.x] += r2[threadIdx.x + s];
        }
        __syncthreads();
    }
    if (threadIdx.x == 0) {
        float n = (float)(V_NODES * 16);
        float m = r1[0] / n;
        float var = r2[0] / n - m * m;
        float rstd = rsqrtf(var + 1e-5f);
        float sc = g[c] * rstd;
        ss[2 * c] = sc;
        ss[2 * c + 1] = be[c] - m * sc;
    }
}

__global__ void __launch_bounds__(256) bnapply_kernel(
    float4* __restrict__ out, const float4* __restrict__ in,
    const float* __restrict__ ss, int C, int n4)
{
    int i = blockIdx.x * 256 + threadIdx.x;
    if (i >= n4) return;
    int c = (i >> 2) % C;
    float sc = ss[2 * c], sh = ss[2 * c + 1];
    float4 v = in[i];
    v.x = fmaxf(v.x, 0.f) * sc + sh;
    v.y = fmaxf(v.y, 0.f) * sc + sh;
    v.z = fmaxf(v.z, 0.f) * sc + sh;
    v.w = fmaxf(v.w, 0.f) * sc + sh;
    out[i] = v;
}

// ---------------------------------------------------------------------------
// Max-pool over V, stage 1: 25 row-chunks of 400, 2048 columns
// ---------------------------------------------------------------------------
__global__ void pool1_kernel(float* __restrict__ pp, const float* __restrict__ h) {
    int col = blockIdx.x * 256 + threadIdx.x;
    int ch = blockIdx.y;
    int v0 = ch * 400;
    float m = -INFINITY;
    for (int v = v0; v < v0 + 400; v++) m = fmaxf(m, h[(size_t)v * 2048 + col]);
    pp[ch * 2048 + col] = m;
}

// ---------------------------------------------------------------------------
// Head: pool reduce + relu, BN over batch, linear 128->10, relu, log_softmax
// ---------------------------------------------------------------------------
__global__ void __launch_bounds__(256) head_kernel(
    float* __restrict__ out, const float* __restrict__ pp,
    const float* __restrict__ g, const float* __restrict__ be,
    const float* __restrict__ lw, const float* __restrict__ lb)
{
    __shared__ float pooled[2048];
    __shared__ float xbn[2048];
    __shared__ float logits[160];
    __shared__ float rowred[16];
    int t = threadIdx.x;

    for (int col = t; col < 2048; col += 256) {
        float m = -INFINITY;
        for (int ch = 0; ch < 25; ch++) m = fmaxf(m, pp[ch * 2048 + col]);
        pooled[col] = fmaxf(m, 0.f);
    }
    __syncthreads();

    if (t < 128) {
        float s1 = 0.f, s2 = 0.f;
        for (int b = 0; b < 16; b++) {
            float x = pooled[t * 16 + b];
            s1 += x; s2 += x * x;
        }
        float m = s1 / 16.f;
        float var = s2 / 16.f - m * m;
        float sc = g[t] * rsqrtf(var + 1e-5f);
        float sh = be[t] - m * sc;
        for (int b = 0; b < 16; b++) xbn[t * 16 + b] = pooled[t * 16 + b] * sc + sh;
    }
    __syncthreads();

    if (t < 160) {
        int b = t / 10, o = t % 10;
        float a = lb[o];
        for (int c = 0; c < 128; c++) a = fmaf(xbn[c * 16 + b], lw[c * 10 + o], a);
        logits[t] = fmaxf(a, 0.f);
    }
    __syncthreads();

    if (t < 16) {
        float m = -INFINITY;
        for (int o = 0; o < 10; o++) m = fmaxf(m, logits[t * 10 + o]);
        float s = 0.f;
        for (int o = 0; o < 10; o++) s += expf(logits[t * 10 + o] - m);
        rowred[t] = m + logf(s);
    }
    __syncthreads();

    if (t < 160) out[t] = logits[t] - rowred[t / 10];
}

// ---------------------------------------------------------------------------
// Host orchestration
// ---------------------------------------------------------------------------
template<int CIN, int COUT>
static constexpr int fused_smem() { return (CIN * 16 + CIN * COUT) * 4; }

extern "C" void kernel_launch(void* const* d_in, const int* in_sizes, int n_in,
                              void* d_out, int out_size) {
    const float* x      = (const float*)d_in[0];
    const float* w_in   = (const float*)d_in[1];
    const float* b_in   = (const float*)d_in[2];
    const float* g1     = (const float*)d_in[3];
    const float* be1    = (const float*)d_in[4];
    const float* w1a    = (const float*)d_in[5];
    const float* b1a    = (const float*)d_in[6];
    const float* g1h    = (const float*)d_in[7];
    const float* be1h   = (const float*)d_in[8];
    const float* w1b    = (const float*)d_in[9];
    const float* b1b    = (const float*)d_in[10];
    const float* sc1    = (const float*)d_in[11];
    const float* g2     = (const float*)d_in[12];
    const float* be2    = (const float*)d_in[13];
    const float* w2a    = (const float*)d_in[14];
    const float* b2a    = (const float*)d_in[15];
    const float* g2h    = (const float*)d_in[16];
    const float* be2h   = (const float*)d_in[17];
    const float* w2b    = (const float*)d_in[18];
    const float* b2b    = (const float*)d_in[19];
    const float* sc2    = (const float*)d_in[20];
    const float* g_out  = (const float*)d_in[21];
    const float* be_out = (const float*)d_in[22];
    const float* lin_w  = (const float*)d_in[23];
    const float* lin_b  = (const float*)d_in[24];
    const float* vals   = (const float*)d_in[25];
    const int*   lidx   = (const int*)d_in[26];
    const int*   col    = lidx + E_EDGES;  // lap_idx[1,:]

    float* base = nullptr;
    cudaGetSymbolAddress((void**)&base, g_buf);
    float* B0 = base;
    float* B1 = base + 1 * BUFSZ;
    float* B2 = base + 2 * BUFSZ;
    float* B3 = base + 3 * BUFSZ;
    float* B4 = base + 4 * BUFSZ;
    float* B5 = base + 5 * BUFSZ;
    float* st0 = base + 6 * BUFSZ;
    float* st1 = st0 + 256;
    float* st2 = st1 + 256;
    float* st3 = st2 + 256;
    float* pp  = st3 + 256;

    // opt-in to >48KB dynamic smem (idempotent host calls; capture-safe)
    cudaFuncSetAttribute(fused_spmm_gemm<128, 128, true>,  cudaFuncAttributeMaxDynamicSharedMemorySize, fused_smem<128, 128>());
    cudaFuncSetAttribute(fused_spmm_gemm<128, 128, false>, cudaFuncAttributeMaxDynamicSharedMemorySize, fused_smem<128, 128>());
    cudaFuncSetAttribute(fused_spmm_gemm<64, 128, true>,   cudaFuncAttributeMaxDynamicSharedMemorySize, fused_smem<64, 128>());
    cudaFuncSetAttribute(fused_spmm_gemm<64, 128, false>,  cudaFuncAttributeMaxDynamicSharedMemorySize, fused_smem<64, 128>());

    // ===== Layer 1: cheb(x, w_in, b_in), Cin=8 Cout=32 =====
    transpose_x_kernel<<<(V_NODES * 128 + 255) / 256, 256>>>(B0, x);
    chebgemm_kernel<8, 32, true><<<V_NODES / 4, 256>>>(B4, B0, w_in, b_in);
    {
        constexpr int SM = fused_smem<8, 32>();
        fused_spmm_gemm<8, 32, true ><<<V_NODES, 256, SM>>>(B1, B0, nullptr, B4, w_in + 1 * 256, col, vals);
        fused_spmm_gemm<8, 32, false><<<V_NODES, 256, SM>>>(B2, B1, B0, B4, w_in + 2 * 256, col, vals);
        fused_spmm_gemm<8, 32, false><<<V_NODES, 256, SM>>>(B0, B2, B1, B4, w_in + 3 * 256, col, vals);
        fused_spmm_gemm<8, 32, false><<<V_NODES, 256, SM>>>(B1, B0, B2, B4, w_in + 4 * 256, col, vals);
        fused_spmm_gemm<8, 32, false><<<V_NODES, 256, SM>>>(B2, B1, B0, B4, w_in + 5 * 256, col, vals);
    }
    // B4 = pre-relu h1 (C=32)

    // ===== Block 1: 32 -> 64 -> 64, shortcut 32->64 =====
    bnstats_kernel<<<32, 256>>>(B4, g1, be1, st0, 32);
    bnapply_kernel<<<(V_NODES * 32 * 4 + 255) / 256, 256>>>((float4*)B3, (const float4*)B4, st0, 32, V_NODES * 32 * 4);
    chebgemm_kernel<32, 64, true><<<V_NODES / 4, 256>>>(B5, B3, w1a, b1a);
    {
        constexpr int SM = fused_smem<32, 64>();
        fused_spmm_gemm<32, 64, true ><<<V_NODES, 256, SM>>>(B1, B3, nullptr, B5, w1a + 1 * 2048, col, vals);
        fused_spmm_gemm<32, 64, false><<<V_NODES, 256, SM>>>(B2, B1, B3, B5, w1a + 2 * 2048, col, vals);
        fused_spmm_gemm<32, 64, false><<<V_NODES, 256, SM>>>(B0, B2, B1, B5, w1a + 3 * 2048, col, vals);
        fused_spmm_gemm<32, 64, false><<<V_NODES, 256, SM>>>(B1, B0, B2, B5, w1a + 4 * 2048, col, vals);
        fused_spmm_gemm<32, 64, false><<<V_NODES, 256, SM>>>(B2, B1, B0, B5, w1a + 5 * 2048, col, vals);
    }
    bnstats_kernel<<<64, 256>>>(B5, g1h, be1h, st1, 64);
    bnapply_kernel<<<(V_NODES * 64 * 4 + 255) / 256, 256>>>((float4*)B0, (const float4*)B5, st1, 64, V_NODES * 64 * 4);
    chebgemm_kernel<64, 64, true><<<V_NODES / 4, 256>>>(B4, B0, w1b, b1b);
    {
        constexpr int SM = fused_smem<64, 64>();
        fused_spmm_gemm<64, 64, true ><<<V_NODES, 256, SM>>>(B1, B0, nullptr, B4, w1b + 1 * 4096, col, vals);
        fused_spmm_gemm<64, 64, false><<<V_NODES, 256, SM>>>(B2, B1, B0, B4, w1b + 2 * 4096, col, vals);
        fused_spmm_gemm<64, 64, false><<<V_NODES, 256, SM>>>(B5, B2, B1, B4, w1b + 3 * 4096, col, vals);
        fused_spmm_gemm<64, 64, false><<<V_NODES, 256, SM>>>(B1, B5, B2, B4, w1b + 4 * 4096, col, vals);
        fused_spmm_gemm<64, 64, false><<<V_NODES, 256, SM>>>(B2, B1, B5, B4, w1b + 5 * 4096, col, vals);
    }
    chebgemm_kernel<32, 64, false><<<V_NODES / 4, 256>>>(B4, B3, sc1, nullptr);
    // B4 = pre-relu block1 out (C=64)

    // ===== Block 2: 64 -> 128 -> 128, shortcut 64->128 =====
    bnstats_kernel<<<64, 256>>>(B4, g2, be2, st2, 64);
    bnapply_kernel<<<(V_NODES * 64 * 4 + 255) / 256, 256>>>((float4*)B3, (const float4*)B4, st2, 64, V_NODES * 64 * 4);
    chebgemm_kernel<64, 128, true><<<V_NODES / 4, 256>>>(B5, B3, w2a, b2a);
    {
        constexpr int SM = fused_smem<64, 128>();
        fused_spmm_gemm<64, 128, true ><<<V_NODES, 256, SM>>>(B1, B3, nullptr, B5, w2a + 1 * 8192, col, vals);
        fused_spmm_gemm<64, 128, false><<<V_NODES, 256, SM>>>(B2, B1, B3, B5, w2a + 2 * 8192, col, vals);
        fused_spmm_gemm<64, 128, false><<<V_NODES, 256, SM>>>(B0, B2, B1, B5, w2a + 3 * 8192, col, vals);
        fused_spmm_gemm<64, 128, false><<<V_NODES, 256, SM>>>(B1, B0, B2, B5, w2a + 4 * 8192, col, vals);
        fused_spmm_gemm<64, 128, false><<<V_NODES, 256, SM>>>(B2, B1, B0, B5, w2a + 5 * 8192, col, vals);
    }
    bnstats_kernel<<<128, 256>>>(B5, g2h, be2h, st3, 128);
    bnapply_kernel<<<(V_NODES * 128 * 4 + 255) / 256, 256>>>((float4*)B0, (const float4*)B5, st3, 128, V_NODES * 128 * 4);
    chebgemm_kernel<128, 128, true><<<V_NODES / 4, 256>>>(B4, B0, w2b, b2b);
    {
        constexpr int SM = fused_smem<128, 128>();
        fused_spmm_gemm<128, 128, true ><<<V_NODES, 256, SM>>>(B1, B0, nullptr, B4, w2b + 1 * 16384, col, vals);
        fused_spmm_gemm<128, 128, false><<<V_NODES, 256, SM>>>(B2, B1, B0, B4, w2b + 2 * 16384, col, vals);
        fused_spmm_gemm<128, 128, false><<<V_NODES, 256, SM>>>(B5, B2, B1, B4, w2b + 3 * 16384, col, vals);
        fused_spmm_gemm<128, 128, false><<<V_NODES, 256, SM>>>(B1, B5, B2, B4, w2b + 4 * 16384, col, vals);
        fused_spmm_gemm<128, 128, false><<<V_NODES, 256, SM>>>(B2, B1, B5, B4, w2b + 5 * 16384, col, vals);
    }
    chebgemm_kernel<64, 128, false><<<V_NODES / 4, 256>>>(B4, B3, sc2, nullptr);
    // B4 = pre-relu final (C=128)

    // ===== Head =====
    pool1_kernel<<<dim3(8, 25), 256>>>(pp, B4);
    head_kernel<<<1, 256>>>((float*)d_out, pp, g_out, be_out, lin_w, lin_b);
}

// round 4
// speedup vs baseline: 1.5715x; 1.4586x over previous
#include <cuda_runtime.h>
#include <cuda_bf16.h>
#include <math.h>

#define V_NODES 10000
#define DEG 32
#define E_EDGES (V_NODES * DEG)

// 6 big rotating buffers of (V, 128*16) floats + bn stats + pool partials
#define BUFSZ (V_NODES * 2048)
__device__ float g_buf[6 * BUFSZ + 4 * 256 + 25 * 2048];

// ---------------------------------------------------------------------------
// transpose input x (B,8,V) -> (V, c*16+b)
// ---------------------------------------------------------------------------
__global__ void transpose_x_kernel(float* __restrict__ out, const float* __restrict__ x) {
    int i = blockIdx.x * 256 + threadIdx.x;
    if (i >= V_NODES * 128) return;
    int b = i & 15;
    int c = (i >> 4) & 7;
    int v = i >> 7;
    out[i] = x[(b * 8 + c) * V_NODES + v];
}

// ---------------------------------------------------------------------------
// GEMM accumulation helper: acc[n][j] += sum_c T[v0+n, c*16+b] * W[c, og+16j]
// Chunked over c in CK=16 steps through shared memory.
// ---------------------------------------------------------------------------
template<int CIN, int COUT, int NV, int OG>
__device__ __forceinline__ void gemm_part(
    float* Ts, float* Ws, float (&acc)[NV][OG],
    const float* __restrict__ T, const float* __restrict__ W,
    int v0, int tid, int b, int og)
{
    constexpr int CK = (CIN < 16) ? CIN : 16;
    for (int c0 = 0; c0 < CIN; c0 += CK) {
        __syncthreads();
        constexpr int TCNT4 = NV * CK * 4;
        for (int i = tid; i < TCNT4; i += 256) {
            int n = i / (CK * 4);
            int r = i - n * (CK * 4);
            ((float4*)Ts)[i] =
                ((const float4*)(T + (size_t)(v0 + n) * CIN * 16 + c0 * 16))[r];
        }
        constexpr int WCNT4 = CK * COUT / 4;
        for (int i = tid; i < WCNT4; i += 256)
            ((float4*)Ws)[i] = ((const float4*)(W + c0 * COUT))[i];
        __syncthreads();
#pragma unroll
        for (int cc = 0; cc < CK; cc++) {
            float tv[NV];
#pragma unroll
            for (int n = 0; n < NV; n++) tv[n] = Ts[n * CK * 16 + cc * 16 + b];
#pragma unroll
            for (int j = 0; j < OG; j++) {
                float wv = Ws[cc * COUT + og + 16 * j];
#pragma unroll
                for (int n = 0; n < NV; n++) acc[n][j] = fmaf(tv[n], wv, acc[n][j]);
            }
        }
    }
}

// ---------------------------------------------------------------------------
// Combined per-term kernel with BLOCK ROLE SPECIALIZATION.
//   blocks [0, NG):        GEMM role:  out[v,:] (+)= T_k[v,:] @ W (+ T2 @ W2)
//   blocks [NG, NG+NS):    SPMM role:  Tnew = L @ Tp1   (FIRST)
//                                       Tnew = 2 L @ Tp1 - Tp2 (otherwise)
// The two roles touch disjoint buffers -> no ordering needed inside a launch.
// GEMM reads T_k == Tp1.
// ---------------------------------------------------------------------------
template<int CIN, int COUT, int CIN2, bool FIRST, bool INIT, bool WITH_SPMM>
__global__ void __launch_bounds__(256) term_kernel(
    float* __restrict__ Tnew, const float* __restrict__ Tp1, const float* __restrict__ Tp2,
    float* __restrict__ out, const float* __restrict__ W, const float* __restrict__ bias,
    const float* __restrict__ T2in, const float* __restrict__ W2,
    const int* __restrict__ col, const float* __restrict__ vals)
{
    constexpr int NV = 4;
    constexpr int NG = V_NODES / NV;
    constexpr int OG = COUT / 16;
    constexpr int F4 = CIN * 4;
    constexpr int TPN = (F4 < 256) ? F4 : 256;
    constexpr int NPB = 256 / TPN;

    __shared__ float smbuf[NV * 16 * 16 + 16 * COUT];

    int tid = threadIdx.x;

    if (blockIdx.x < NG) {
        // ---------------- GEMM role ----------------
        float* Ts = smbuf;
        float* Ws = smbuf + NV * 16 * 16;
        int b = tid & 15;
        int og = tid >> 4;
        int v0 = blockIdx.x * NV;

        float acc[NV][OG];
#pragma unroll
        for (int j = 0; j < OG; j++) {
            float bv = INIT ? bias[og + 16 * j] : 0.f;
#pragma unroll
            for (int n = 0; n < NV; n++) acc[n][j] = bv;
        }

        gemm_part<CIN, COUT, NV, OG>(Ts, Ws, acc, Tp1, W, v0, tid, b, og);
        if (CIN2 > 0)
            gemm_part<(CIN2 > 0 ? CIN2 : 16), COUT, NV, OG>(Ts, Ws, acc, T2in, W2, v0, tid, b, og);

#pragma unroll
        for (int n = 0; n < NV; n++)
#pragma unroll
            for (int j = 0; j < OG; j++) {
                size_t idx = (size_t)(v0 + n) * COUT * 16 + (size_t)(og + 16 * j) * 16 + b;
                if (INIT) out[idx] = acc[n][j];
                else      out[idx] += acc[n][j];
            }
    } else if (WITH_SPMM) {
        // ---------------- SPMM role ----------------
        int sb = blockIdx.x - NG;
        int* scol = (int*)smbuf;
        float* sval = smbuf + NPB * DEG;
        int v0 = sb * NPB;
        if (tid < NPB * DEG) {
            scol[tid] = col[v0 * DEG + tid];
            sval[tid] = vals[v0 * DEG + tid];
        }
        __syncthreads();

        int ln = tid / TPN;      // node within block
        int v = v0 + ln;
        int f0 = tid - ln * TPN;

        const float4* z4 = (const float4*)Tp1;
        const float4* p4 = (const float4*)Tp2;
        float4* y4 = (float4*)Tnew;

        for (int f = f0; f < F4; f += TPN) {
            float4 acc = make_float4(0.f, 0.f, 0.f, 0.f);
#pragma unroll 8
            for (int e = 0; e < DEG; e++) {
                float w = sval[ln * DEG + e];
                float4 zz = z4[(size_t)scol[ln * DEG + e] * F4 + f];
                acc.x = fmaf(w, zz.x, acc.x);
                acc.y = fmaf(w, zz.y, acc.y);
                acc.z = fmaf(w, zz.z, acc.z);
                acc.w = fmaf(w, zz.w, acc.w);
            }
            if (!FIRST) {
                float4 p = p4[(size_t)v * F4 + f];
                acc.x = 2.f * acc.x - p.x;
                acc.y = 2.f * acc.y - p.y;
                acc.z = 2.f * acc.z - p.z;
                acc.w = 2.f * acc.w - p.w;
            }
            y4[(size_t)v * F4 + f] = acc;
        }
    }
}

// host-side grid helper
static inline int ns_for(int cin) {
    int f4 = cin * 4;
    int tpn = (f4 < 256) ? f4 : 256;
    return V_NODES / (256 / tpn);
}

// ---------------------------------------------------------------------------
// BatchNorm stats (training mode) over (B,V) per channel, with relu-on-read.
// ---------------------------------------------------------------------------
__global__ void __launch_bounds__(256) bnstats_kernel(
    const float* __restrict__ h, const float* __restrict__ g,
    const float* __restrict__ be, float* __restrict__ ss, int C)
{
    int c = blockIdx.x;
    int F = C * 16;
    float s1 = 0.f, s2 = 0.f;
    for (int k = threadIdx.x; k < V_NODES * 16; k += 256) {
        int v = k >> 4, b = k & 15;
        float x = h[(size_t)v * F + c * 16 + b];
        x = fmaxf(x, 0.f);
        s1 += x;
        s2 += x * x;
    }
    __shared__ float r1[256], r2[256];
    r1[threadIdx.x] = s1; r2[threadIdx.x] = s2;
    __syncthreads();
    for (int s = 128; s > 0; s >>= 1) {
        if (threadIdx.x < s) {
            r1[threadIdx.x] += r1[threadIdx.x + s];
            r2[threadIdx.x] += r2[threadIdx.x + s];
        }
        __syncthreads();
    }
    if (threadIdx.x == 0) {
        float n = (float)(V_NODES * 16);
        float m = r1[0] / n;
        float var = r2[0] / n - m * m;
        float rstd = rsqrtf(var + 1e-5f);
        float sc = g[c] * rstd;
        ss[2 * c] = sc;
        ss[2 * c + 1] = be[c] - m * sc;
    }
}

__global__ void __launch_bounds__(256) bnapply_kernel(
    float4* __restrict__ out, const float4* __restrict__ in,
    const float* __restrict__ ss, int C, int n4)
{
    int i = blockIdx.x * 256 + threadIdx.x;
    if (i >= n4) return;
    int c = (i >> 2) % C;
    float sc = ss[2 * c], sh = ss[2 * c + 1];
    float4 v = in[i];
    v.x = fmaxf(v.x, 0.f) * sc + sh;
    v.y = fmaxf(v.y, 0.f) * sc + sh;
    v.z = fmaxf(v.z, 0.f) * sc + sh;
    v.w = fmaxf(v.w, 0.f) * sc + sh;
    out[i] = v;
}

// ---------------------------------------------------------------------------
// Max-pool over V, stage 1: 25 row-chunks of 400, 2048 columns
// ---------------------------------------------------------------------------
__global__ void pool1_kernel(float* __restrict__ pp, const float* __restrict__ h) {
    int col = blockIdx.x * 256 + threadIdx.x;
    int ch = blockIdx.y;
    int v0 = ch * 400;
    float m = -INFINITY;
    for (int v = v0; v < v0 + 400; v++) m = fmaxf(m, h[(size_t)v * 2048 + col]);
    pp[ch * 2048 + col] = m;
}

// ---------------------------------------------------------------------------
// Head: pool reduce + relu, BN over batch, linear 128->10, relu, log_softmax
// ---------------------------------------------------------------------------
__global__ void __launch_bounds__(256) head_kernel(
    float* __restrict__ out, const float* __restrict__ pp,
    const float* __restrict__ g, const float* __restrict__ be,
    const float* __restrict__ lw, const float* __restrict__ lb)
{
    __shared__ float pooled[2048];
    __shared__ float xbn[2048];
    __shared__ float logits[160];
    __shared__ float rowred[16];
    int t = threadIdx.x;

    for (int col = t; col < 2048; col += 256) {
        float m = -INFINITY;
        for (int ch = 0; ch < 25; ch++) m = fmaxf(m, pp[ch * 2048 + col]);
        pooled[col] = fmaxf(m, 0.f);
    }
    __syncthreads();

    if (t < 128) {
        float s1 = 0.f, s2 = 0.f;
        for (int b = 0; b < 16; b++) {
            float x = pooled[t * 16 + b];
            s1 += x; s2 += x * x;
        }
        float m = s1 / 16.f;
        float var = s2 / 16.f - m * m;
        float sc = g[t] * rsqrtf(var + 1e-5f);
        float sh = be[t] - m * sc;
        for (int b = 0; b < 16; b++) xbn[t * 16 + b] = pooled[t * 16 + b] * sc + sh;
    }
    __syncthreads();

    if (t < 160) {
        int b = t / 10, o = t % 10;
        float a = lb[o];
        for (int c = 0; c < 128; c++) a = fmaf(xbn[c * 16 + b], lw[c * 10 + o], a);
        logits[t] = fmaxf(a, 0.f);
    }
    __syncthreads();

    if (t < 16) {
        float m = -INFINITY;
        for (int o = 0; o < 10; o++) m = fmaxf(m, logits[t * 10 + o]);
        float s = 0.f;
        for (int o = 0; o < 10; o++) s += expf(logits[t * 10 + o] - m);
        rowred[t] = m + logf(s);
    }
    __syncthreads();

    if (t < 160) out[t] = logits[t] - rowred[t / 10];
}

// ---------------------------------------------------------------------------
// Host orchestration
// ---------------------------------------------------------------------------
extern "C" void kernel_launch(void* const* d_in, const int* in_sizes, int n_in,
                              void* d_out, int out_size) {
    const float* x      = (const float*)d_in[0];
    const float* w_in   = (const float*)d_in[1];
    const float* b_in   = (const float*)d_in[2];
    const float* g1     = (const float*)d_in[3];
    const float* be1    = (const float*)d_in[4];
    const float* w1a    = (const float*)d_in[5];
    const float* b1a    = (const float*)d_in[6];
    const float* g1h    = (const float*)d_in[7];
    const float* be1h   = (const float*)d_in[8];
    const float* w1b    = (const float*)d_in[9];
    const float* b1b    = (const float*)d_in[10];
    const float* sc1    = (const float*)d_in[11];
    const float* g2     = (const float*)d_in[12];
    const float* be2    = (const float*)d_in[13];
    const float* w2a    = (const float*)d_in[14];
    const float* b2a    = (const float*)d_in[15];
    const float* g2h    = (const float*)d_in[16];
    const float* be2h   = (const float*)d_in[17];
    const float* w2b    = (const float*)d_in[18];
    const float* b2b    = (const float*)d_in[19];
    const float* sc2    = (const float*)d_in[20];
    const float* g_out  = (const float*)d_in[21];
    const float* be_out = (const float*)d_in[22];
    const float* lin_w  = (const float*)d_in[23];
    const float* lin_b  = (const float*)d_in[24];
    const float* vals   = (const float*)d_in[25];
    const int*   lidx   = (const int*)d_in[26];
    const int*   col    = lidx + E_EDGES;  // lap_idx[1,:]

    float* base = nullptr;
    cudaGetSymbolAddress((void**)&base, g_buf);
    float* B0 = base;
    float* B1 = base + 1 * BUFSZ;
    float* B2 = base + 2 * BUFSZ;
    float* B3 = base + 3 * BUFSZ;
    float* B4 = base + 4 * BUFSZ;
    float* B5 = base + 5 * BUFSZ;
    float* st0 = base + 6 * BUFSZ;
    float* st1 = st0 + 256;
    float* st2 = st1 + 256;
    float* st3 = st2 + 256;
    float* pp  = st3 + 256;

    const int NG = V_NODES / 4;

    // ===== Layer 1: cheb(x, w_in, b_in), Cin=8 Cout=32, out=B4 =====
    // rotation: T0=B0 T1=B1 T2=B2 T3=B0 T4=B1 T5=B2
    transpose_x_kernel<<<(V_NODES * 128 + 255) / 256, 256>>>(B0, x);
    {
        const int NS = ns_for(8), G = NG + NS;
        term_kernel<8, 32, 0, true,  true,  true ><<<G, 256>>>(B1, B0, nullptr, B4, w_in,            b_in,   nullptr, nullptr, col, vals);
        term_kernel<8, 32, 0, false, false, true ><<<G, 256>>>(B2, B1, B0,      B4, w_in + 1 * 256, nullptr, nullptr, nullptr, col, vals);
        term_kernel<8, 32, 0, false, false, true ><<<G, 256>>>(B0, B2, B1,      B4, w_in + 2 * 256, nullptr, nullptr, nullptr, col, vals);
        term_kernel<8, 32, 0, false, false, true ><<<G, 256>>>(B1, B0, B2,      B4, w_in + 3 * 256, nullptr, nullptr, nullptr, col, vals);
        term_kernel<8, 32, 0, false, false, true ><<<G, 256>>>(B2, B1, B0,      B4, w_in + 4 * 256, nullptr, nullptr, nullptr, col, vals);
        term_kernel<8, 32, 0, false, false, false><<<NG, 256>>>(nullptr, B2, nullptr, B4, w_in + 5 * 256, nullptr, nullptr, nullptr, col, vals);
    }

    // ===== Block 1 =====
    bnstats_kernel<<<32, 256>>>(B4, g1, be1, st0, 32);
    bnapply_kernel<<<(V_NODES * 32 * 4 + 255) / 256, 256>>>((float4*)B3, (const float4*)B4, st0, 32, V_NODES * 32 * 4);
    // chebA: 32 -> 64, in=B3 (kept), out=B5; T0=B3 T1=B1 T2=B2 T3=B0 T4=B1 T5=B2
    {
        const int NS = ns_for(32), G = NG + NS;
        term_kernel<32, 64, 0, true,  true,  true ><<<G, 256>>>(B1, B3, nullptr, B5, w1a,            b1a,    nullptr, nullptr, col, vals);
        term_kernel<32, 64, 0, false, false, true ><<<G, 256>>>(B2, B1, B3,      B5, w1a + 1 * 2048, nullptr, nullptr, nullptr, col, vals);
        term_kernel<32, 64, 0, false, false, true ><<<G, 256>>>(B0, B2, B1,      B5, w1a + 2 * 2048, nullptr, nullptr, nullptr, col, vals);
        term_kernel<32, 64, 0, false, false, true ><<<G, 256>>>(B1, B0, B2,      B5, w1a + 3 * 2048, nullptr, nullptr, nullptr, col, vals);
        term_kernel<32, 64, 0, false, false, true ><<<G, 256>>>(B2, B1, B0,      B5, w1a + 4 * 2048, nullptr, nullptr, nullptr, col, vals);
        term_kernel<32, 64, 0, false, false, false><<<NG, 256>>>(nullptr, B2, nullptr, B5, w1a + 5 * 2048, nullptr, nullptr, nullptr, col, vals);
    }
    bnstats_kernel<<<64, 256>>>(B5, g1h, be1h, st1, 64);
    bnapply_kernel<<<(V_NODES * 64 * 4 + 255) / 256, 256>>>((float4*)B0, (const float4*)B5, st1, 64, V_NODES * 64 * 4);
    // chebB: 64 -> 64 (+ shortcut B3@sc1 folded into k=0), in=B0, out=B4
    // T0=B0 T1=B1 T2=B2 T3=B5 T4=B1 T5=B2
    {
        const int NS = ns_for(64), G = NG + NS;
        term_kernel<64, 64, 32, true,  true,  true ><<<G, 256>>>(B1, B0, nullptr, B4, w1b,            b1b,    B3, sc1, col, vals);
        term_kernel<64, 64, 0,  false, false, true ><<<G, 256>>>(B2, B1, B0,      B4, w1b + 1 * 4096, nullptr, nullptr, nullptr, col, vals);
        term_kernel<64, 64, 0,  false, false, true ><<<G, 256>>>(B5, B2, B1,      B4, w1b + 2 * 4096, nullptr, nullptr, nullptr, col, vals);
        term_kernel<64, 64, 0,  false, false, true ><<<G, 256>>>(B1, B5, B2,      B4, w1b + 3 * 4096, nullptr, nullptr, nullptr, col, vals);
        term_kernel<64, 64, 0,  false, false, true ><<<G, 256>>>(B2, B1, B5,      B4, w1b + 4 * 4096, nullptr, nullptr, nullptr, col, vals);
        term_kernel<64, 64, 0,  false, false, false><<<NG, 256>>>(nullptr, B2, nullptr, B4, w1b + 5 * 4096, nullptr, nullptr, nullptr, col, vals);
    }

    // ===== Block 2 =====
    bnstats_kernel<<<64, 256>>>(B4, g2, be2, st2, 64);
    bnapply_kernel<<<(V_NODES * 64 * 4 + 255) / 256, 256>>>((float4*)B3, (const float4*)B4, st2, 64, V_NODES * 64 * 4);
    // chebA: 64 -> 128, in=B3 (kept), out=B5; T0=B3 T1=B1 T2=B2 T3=B0 T4=B1 T5=B2
    {
        const int NS = ns_for(64), G = NG + NS;
        term_kernel<64, 128, 0, true,  true,  true ><<<G, 256>>>(B1, B3, nullptr, B5, w2a,            b2a,    nullptr, nullptr, col, vals);
        term_kernel<64, 128, 0, false, false, true ><<<G, 256>>>(B2, B1, B3,      B5, w2a + 1 * 8192, nullptr, nullptr, nullptr, col, vals);
        term_kernel<64, 128, 0, false, false, true ><<<G, 256>>>(B0, B2, B1,      B5, w2a + 2 * 8192, nullptr, nullptr, nullptr, col, vals);
        term_kernel<64, 128, 0, false, false, true ><<<G, 256>>>(B1, B0, B2,      B5, w2a + 3 * 8192, nullptr, nullptr, nullptr, col, vals);
        term_kernel<64, 128, 0, false, false, true ><<<G, 256>>>(B2, B1, B0,      B5, w2a + 4 * 8192, nullptr, nullptr, nullptr, col, vals);
        term_kernel<64, 128, 0, false, false, false><<<NG, 256>>>(nullptr, B2, nullptr, B5, w2a + 5 * 8192, nullptr, nullptr, nullptr, col, vals);
    }
    bnstats_kernel<<<128, 256>>>(B5, g2h, be2h, st3, 128);
    bnapply_kernel<<<(V_NODES * 128 * 4 + 255) / 256, 256>>>((float4*)B0, (const float4*)B5, st3, 128, V_NODES * 128 * 4);
    // chebB: 128 -> 128 (+ shortcut B3@sc2 folded into k=0), in=B0, out=B4
    // T0=B0 T1=B1 T2=B2 T3=B5 T4=B1 T5=B2
    {
        const int NS = ns_for(128), G = NG + NS;
        term_kernel<128, 128, 64, true,  true,  true ><<<G, 256>>>(B1, B0, nullptr, B4, w2b,             b2b,    B3, sc2, col, vals);
        term_kernel<128, 128, 0,  false, false, true ><<<G, 256>>>(B2, B1, B0,      B4, w2b + 1 * 16384, nullptr, nullptr, nullptr, col, vals);
        term_kernel<128, 128, 0,  false, false, true ><<<G, 256>>>(B5, B2, B1,      B4, w2b + 2 * 16384, nullptr, nullptr, nullptr, col, vals);
        term_kernel<128, 128, 0,  false, false, true ><<<G, 256>>>(B1, B5, B2,      B4, w2b + 3 * 16384, nullptr, nullptr, nullptr, col, vals);
        term_kernel<128, 128, 0,  false, false, true ><<<G, 256>>>(B2, B1, B5,      B4, w2b + 4 * 16384, nullptr, nullptr, nullptr, col, vals);
        term_kernel<128, 128, 0,  false, false, false><<<NG, 256>>>(nullptr, B2, nullptr, B4, w2b + 5 * 16384, nullptr, nullptr, nullptr, col, vals);
    }

    // ===== Head =====
    pool1_kernel<<<dim3(8, 25), 256>>>(pp, B4);
    head_kernel<<<1, 256>>>((float*)d_out, pp, g_out, be_out, lin_w, lin_b);
}

// round 6
// speedup vs baseline: 1.9089x; 1.2147x over previous
#include <cuda_runtime.h>
#include <cuda_fp16.h>
#include <math.h>

#define V_NODES 10000
#define DEG 32
#define E_EDGES (V_NODES * DEG)

// 6 rotating buffers (T buffers used as fp16, out buffers as fp32) + stats + pool
#define BUFSZ (V_NODES * 2048)
__device__ float g_buf[6 * BUFSZ + 4 * 256 + 25 * 2048];

// ---------------------------------------------------------------------------
// transpose input x (B,8,V) -> fp16 (V, c*16+b)
// ---------------------------------------------------------------------------
__global__ void transpose_x_kernel(__half* __restrict__ out, const float* __restrict__ x) {
    int i = blockIdx.x * 256 + threadIdx.x;
    if (i >= V_NODES * 128) return;
    int b = i & 15;
    int c = (i >> 4) & 7;
    int v = i >> 7;
    out[i] = __float2half(x[(b * 8 + c) * V_NODES + v]);
}

// ---------------------------------------------------------------------------
// GEMM accumulation helper: acc[n][j] += sum_c T[v0+n, c*16+b] * W[c, og+16j]
// T is fp16 in gmem; converted to fp32 while staging into smem.
// ---------------------------------------------------------------------------
template<int CIN, int COUT, int NV, int OG>
__device__ __forceinline__ void gemm_part(
    float* Ts, float* Ws, float (&acc)[NV][OG],
    const __half* __restrict__ T, const float* __restrict__ W,
    int v0, int tid, int b, int og)
{
    constexpr int CK = (CIN < 16) ? CIN : 16;
    for (int c0 = 0; c0 < CIN; c0 += CK) {
        __syncthreads();
        constexpr int TCNT = NV * CK * 2;   // uint4s (8 halves each)
        for (int i = tid; i < TCNT; i += 256) {
            int n = i / (CK * 2);
            int r = i - n * (CK * 2);
            uint4 raw = ((const uint4*)(T + (size_t)(v0 + n) * CIN * 16 + c0 * 16))[r];
            const __half2* h2 = (const __half2*)&raw;
            float* dst = Ts + n * CK * 16 + r * 8;
#pragma unroll
            for (int j = 0; j < 4; j++) {
                float2 f = __half22float2(h2[j]);
                dst[2 * j] = f.x;
                dst[2 * j + 1] = f.y;
            }
        }
        constexpr int WCNT4 = CK * COUT / 4;
        for (int i = tid; i < WCNT4; i += 256)
            ((float4*)Ws)[i] = ((const float4*)(W + c0 * COUT))[i];
        __syncthreads();
#pragma unroll
        for (int cc = 0; cc < CK; cc++) {
            float tv[NV];
#pragma unroll
            for (int n = 0; n < NV; n++) tv[n] = Ts[n * CK * 16 + cc * 16 + b];
#pragma unroll
            for (int j = 0; j < OG; j++) {
                float wv = Ws[cc * COUT + og + 16 * j];
#pragma unroll
                for (int n = 0; n < NV; n++) acc[n][j] = fmaf(tv[n], wv, acc[n][j]);
            }
        }
    }
}

// ---------------------------------------------------------------------------
// Combined per-term kernel with BLOCK ROLE SPECIALIZATION.
//   blocks [0, NG):     GEMM role:  out[v,:] (+)= T_k[v,:] @ W (+ T2 @ W2)  (fp32 out)
//   blocks [NG, NG+NS): SPMM role:  Tnew = L @ Tp1 (FIRST) | 2 L @ Tp1 - Tp2
//                       all T buffers fp16; accumulate fp32
// ---------------------------------------------------------------------------
template<int CIN, int COUT, int CIN2, bool FIRST, bool INIT, bool WITH_SPMM>
__global__ void __launch_bounds__(256) term_kernel(
    __half* __restrict__ Tnew, const __half* __restrict__ Tp1, const __half* __restrict__ Tp2,
    float* __restrict__ out, const float* __restrict__ W, const float* __restrict__ bias,
    const __half* __restrict__ T2in, const float* __restrict__ W2,
    const int* __restrict__ col, const float* __restrict__ vals)
{
    constexpr int NV = 4;
    constexpr int NG = V_NODES / NV;
    constexpr int OG = COUT / 16;
    constexpr int F8 = CIN * 2;                 // row length in uint4 (8 halves)
    constexpr int TPN = (F8 < 256) ? F8 : 256;  // threads per node (spmm)
    constexpr int NPB = 256 / TPN;              // nodes per spmm block

    // shared buffer must fit both roles:
    //   gemm: NV*16*16 + 16*COUT floats
    //   spmm: NPB*DEG ints + NPB*DEG floats
    constexpr int SM_GEMM = NV * 16 * 16 + 16 * COUT;
    constexpr int SM_SPMM = 2 * NPB * DEG;
    constexpr int SM_SIZE = (SM_GEMM > SM_SPMM) ? SM_GEMM : SM_SPMM;
    __shared__ float smbuf[SM_SIZE];

    int tid = threadIdx.x;

    if (blockIdx.x < NG) {
        // ---------------- GEMM role ----------------
        float* Ts = smbuf;
        float* Ws = smbuf + NV * 16 * 16;
        int b = tid & 15;
        int og = tid >> 4;
        int v0 = blockIdx.x * NV;

        float acc[NV][OG];
#pragma unroll
        for (int j = 0; j < OG; j++) {
            float bv = INIT ? bias[og + 16 * j] : 0.f;
#pragma unroll
            for (int n = 0; n < NV; n++) acc[n][j] = bv;
        }

        gemm_part<CIN, COUT, NV, OG>(Ts, Ws, acc, Tp1, W, v0, tid, b, og);
        if (CIN2 > 0)
            gemm_part<(CIN2 > 0 ? CIN2 : 16), COUT, NV, OG>(Ts, Ws, acc, T2in, W2, v0, tid, b, og);

#pragma unroll
        for (int n = 0; n < NV; n++)
#pragma unroll
            for (int j = 0; j < OG; j++) {
                size_t idx = (size_t)(v0 + n) * COUT * 16 + (size_t)(og + 16 * j) * 16 + b;
                if (INIT) out[idx] = acc[n][j];
                else      out[idx] += acc[n][j];
            }
    } else if (WITH_SPMM) {
        // ---------------- SPMM role ----------------
        int sb = blockIdx.x - NG;
        int* scol = (int*)smbuf;
        float* sval = smbuf + NPB * DEG;
        int v0 = sb * NPB;
        for (int i = tid; i < NPB * DEG; i += 256) {     // FIX: strided (NPB*DEG can be 512)
            scol[i] = col[v0 * DEG + i];
            sval[i] = vals[v0 * DEG + i];
        }
        __syncthreads();

        int ln = tid / TPN;      // node within block
        int v = v0 + ln;
        int f0 = tid - ln * TPN;

        const uint4* z4 = (const uint4*)Tp1;
        const uint4* p4 = (const uint4*)Tp2;
        uint4* y4 = (uint4*)Tnew;

        for (int f = f0; f < F8; f += TPN) {
            float acc[8];
#pragma unroll
            for (int i = 0; i < 8; i++) acc[i] = 0.f;
#pragma unroll 8
            for (int e = 0; e < DEG; e++) {
                float w = sval[ln * DEG + e];
                uint4 raw = z4[(size_t)scol[ln * DEG + e] * F8 + f];
                const __half2* h2 = (const __half2*)&raw;
#pragma unroll
                for (int i = 0; i < 4; i++) {
                    float2 zz = __half22float2(h2[i]);
                    acc[2 * i]     = fmaf(w, zz.x, acc[2 * i]);
                    acc[2 * i + 1] = fmaf(w, zz.y, acc[2 * i + 1]);
                }
            }
            if (!FIRST) {
                uint4 raw = p4[(size_t)v * F8 + f];
                const __half2* h2 = (const __half2*)&raw;
#pragma unroll
                for (int i = 0; i < 4; i++) {
                    float2 p = __half22float2(h2[i]);
                    acc[2 * i]     = 2.f * acc[2 * i]     - p.x;
                    acc[2 * i + 1] = 2.f * acc[2 * i + 1] - p.y;
                }
            }
            uint4 o;
            __half2* oh = (__half2*)&o;
#pragma unroll
            for (int i = 0; i < 4; i++)
                oh[i] = __floats2half2_rn(acc[2 * i], acc[2 * i + 1]);
            y4[(size_t)v * F8 + f] = o;
        }
    }
}

// host-side grid helper
static inline int ns_for(int cin) {
    int f8 = cin * 2;
    int tpn = (f8 < 256) ? f8 : 256;
    return V_NODES / (256 / tpn);
}

// ---------------------------------------------------------------------------
// BatchNorm stats (training mode) over (B,V) per channel, with relu-on-read.
// ---------------------------------------------------------------------------
__global__ void __launch_bounds__(256) bnstats_kernel(
    const float* __restrict__ h, const float* __restrict__ g,
    const float* __restrict__ be, float* __restrict__ ss, int C)
{
    int c = blockIdx.x;
    int F = C * 16;
    float s1 = 0.f, s2 = 0.f;
    for (int k = threadIdx.x; k < V_NODES * 16; k += 256) {
        int v = k >> 4, b = k & 15;
        float x = h[(size_t)v * F + c * 16 + b];
        x = fmaxf(x, 0.f);
        s1 += x;
        s2 += x * x;
    }
    __shared__ float r1[256], r2[256];
    r1[threadIdx.x] = s1; r2[threadIdx.x] = s2;
    __syncthreads();
    for (int s = 128; s > 0; s >>= 1) {
        if (threadIdx.x < s) {
            r1[threadIdx.x] += r1[threadIdx.x + s];
            r2[threadIdx.x] += r2[threadIdx.x + s];
        }
        __syncthreads();
    }
    if (threadIdx.x == 0) {
        float n = (float)(V_NODES * 16);
        float m = r1[0] / n;
        float var = r2[0] / n - m * m;
        float rstd = rsqrtf(var + 1e-5f);
        float sc = g[c] * rstd;
        ss[2 * c] = sc;
        ss[2 * c + 1] = be[c] - m * sc;
    }
}

// bn apply: fp32 in -> fp16 out (next layer's T0)
__global__ void __launch_bounds__(256) bnapply_kernel(
    __half2* __restrict__ out, const float4* __restrict__ in,
    const float* __restrict__ ss, int C, int n4)
{
    int i = blockIdx.x * 256 + threadIdx.x;
    if (i >= n4) return;
    int c = (i >> 2) % C;
    float sc = ss[2 * c], sh = ss[2 * c + 1];
    float4 v = in[i];
    v.x = fmaxf(v.x, 0.f) * sc + sh;
    v.y = fmaxf(v.y, 0.f) * sc + sh;
    v.z = fmaxf(v.z, 0.f) * sc + sh;
    v.w = fmaxf(v.w, 0.f) * sc + sh;
    out[2 * i]     = __floats2half2_rn(v.x, v.y);
    out[2 * i + 1] = __floats2half2_rn(v.z, v.w);
}

// ---------------------------------------------------------------------------
// Max-pool over V, stage 1: 25 row-chunks of 400, 2048 columns
// ---------------------------------------------------------------------------
__global__ void pool1_kernel(float* __restrict__ pp, const float* __restrict__ h) {
    int col = blockIdx.x * 256 + threadIdx.x;
    int ch = blockIdx.y;
    int v0 = ch * 400;
    float m = -INFINITY;
    for (int v = v0; v < v0 + 400; v++) m = fmaxf(m, h[(size_t)v * 2048 + col]);
    pp[ch * 2048 + col] = m;
}

// ---------------------------------------------------------------------------
// Head: pool reduce + relu, BN over batch, linear 128->10, relu, log_softmax
// ---------------------------------------------------------------------------
__global__ void __launch_bounds__(256) head_kernel(
    float* __restrict__ out, const float* __restrict__ pp,
    const float* __restrict__ g, const float* __restrict__ be,
    const float* __restrict__ lw, const float* __restrict__ lb)
{
    __shared__ float pooled[2048];
    __shared__ float xbn[2048];
    __shared__ float logits[160];
    __shared__ float rowred[16];
    int t = threadIdx.x;

    for (int col = t; col < 2048; col += 256) {
        float m = -INFINITY;
        for (int ch = 0; ch < 25; ch++) m = fmaxf(m, pp[ch * 2048 + col]);
        pooled[col] = fmaxf(m, 0.f);
    }
    __syncthreads();

    if (t < 128) {
        float s1 = 0.f, s2 = 0.f;
        for (int b = 0; b < 16; b++) {
            float x = pooled[t * 16 + b];
            s1 += x; s2 += x * x;
        }
        float m = s1 / 16.f;
        float var = s2 / 16.f - m * m;
        float sc = g[t] * rsqrtf(var + 1e-5f);
        float sh = be[t] - m * sc;
        for (int b = 0; b < 16; b++) xbn[t * 16 + b] = pooled[t * 16 + b] * sc + sh;
    }
    __syncthreads();

    if (t < 160) {
        int b = t / 10, o = t % 10;
        float a = lb[o];
        for (int c = 0; c < 128; c++) a = fmaf(xbn[c * 16 + b], lw[c * 10 + o], a);
        logits[t] = fmaxf(a, 0.f);
    }
    __syncthreads();

    if (t < 16) {
        float m = -INFINITY;
        for (int o = 0; o < 10; o++) m = fmaxf(m, logits[t * 10 + o]);
        float s = 0.f;
        for (int o = 0; o < 10; o++) s += expf(logits[t * 10 + o] - m);
        rowred[t] = m + logf(s);
    }
    __syncthreads();

    if (t < 160) out[t] = logits[t] - rowred[t / 10];
}

// ---------------------------------------------------------------------------
// Host orchestration
// ---------------------------------------------------------------------------
extern "C" void kernel_launch(void* const* d_in, const int* in_sizes, int n_in,
                              void* d_out, int out_size) {
    const float* x      = (const float*)d_in[0];
    const float* w_in   = (const float*)d_in[1];
    const float* b_in   = (const float*)d_in[2];
    const float* g1     = (const float*)d_in[3];
    const float* be1    = (const float*)d_in[4];
    const float* w1a    = (const float*)d_in[5];
    const float* b1a    = (const float*)d_in[6];
    const float* g1h    = (const float*)d_in[7];
    const float* be1h   = (const float*)d_in[8];
    const float* w1b    = (const float*)d_in[9];
    const float* b1b    = (const float*)d_in[10];
    const float* sc1    = (const float*)d_in[11];
    const float* g2     = (const float*)d_in[12];
    const float* be2    = (const float*)d_in[13];
    const float* w2a    = (const float*)d_in[14];
    const float* b2a    = (const float*)d_in[15];
    const float* g2h    = (const float*)d_in[16];
    const float* be2h   = (const float*)d_in[17];
    const float* w2b    = (const float*)d_in[18];
    const float* b2b    = (const float*)d_in[19];
    const float* sc2    = (const float*)d_in[20];
    const float* g_out  = (const float*)d_in[21];
    const float* be_out = (const float*)d_in[22];
    const float* lin_w  = (const float*)d_in[23];
    const float* lin_b  = (const float*)d_in[24];
    const float* vals   = (const float*)d_in[25];
    const int*   lidx   = (const int*)d_in[26];
    const int*   col    = lidx + E_EDGES;  // lap_idx[1,:]

    float* base = nullptr;
    cudaGetSymbolAddress((void**)&base, g_buf);
    // T buffers (fp16 view) and out buffers (fp32)
    __half* H0 = (__half*)(base + 0 * BUFSZ);
    __half* H1 = (__half*)(base + 1 * BUFSZ);
    __half* H2 = (__half*)(base + 2 * BUFSZ);
    __half* H3 = (__half*)(base + 3 * BUFSZ);
    float*  B4 = base + 4 * BUFSZ;   // out accumulator A
    float*  B5 = base + 5 * BUFSZ;   // out accumulator B
    __half* H5 = (__half*)(base + 3 * BUFSZ + BUFSZ / 2);  // upper half of slot 3 region
    float* st0 = base + 6 * BUFSZ;
    float* st1 = st0 + 256;
    float* st2 = st1 + 256;
    float* st3 = st2 + 256;
    float* pp  = st3 + 256;

    const int NG = V_NODES / 4;

    // ===== Layer 1: cheb(x, w_in, b_in), Cin=8 Cout=32, out=B4 =====
    transpose_x_kernel<<<(V_NODES * 128 + 255) / 256, 256>>>(H0, x);
    {
        const int NS = ns_for(8), G = NG + NS;
        term_kernel<8, 32, 0, true,  true,  true ><<<G, 256>>>(H1, H0, nullptr, B4, w_in,            b_in,   nullptr, nullptr, col, vals);
        term_kernel<8, 32, 0, false, false, true ><<<G, 256>>>(H2, H1, H0,      B4, w_in + 1 * 256, nullptr, nullptr, nullptr, col, vals);
        term_kernel<8, 32, 0, false, false, true ><<<G, 256>>>(H0, H2, H1,      B4, w_in + 2 * 256, nullptr, nullptr, nullptr, col, vals);
        term_kernel<8, 32, 0, false, false, true ><<<G, 256>>>(H1, H0, H2,      B4, w_in + 3 * 256, nullptr, nullptr, nullptr, col, vals);
        term_kernel<8, 32, 0, false, false, true ><<<G, 256>>>(H2, H1, H0,      B4, w_in + 4 * 256, nullptr, nullptr, nullptr, col, vals);
        term_kernel<8, 32, 0, false, false, false><<<NG, 256>>>(nullptr, H2, nullptr, B4, w_in + 5 * 256, nullptr, nullptr, nullptr, col, vals);
    }

    // ===== Block 1 =====
    bnstats_kernel<<<32, 256>>>(B4, g1, be1, st0, 32);
    bnapply_kernel<<<(V_NODES * 32 * 4 + 255) / 256, 256>>>((__half2*)H3, (const float4*)B4, st0, 32, V_NODES * 32 * 4);
    // chebA: 32 -> 64, in=H3 (kept for shortcut), out=B5
    {
        const int NS = ns_for(32), G = NG + NS;
        term_kernel<32, 64, 0, true,  true,  true ><<<G, 256>>>(H1, H3, nullptr, B5, w1a,            b1a,    nullptr, nullptr, col, vals);
        term_kernel<32, 64, 0, false, false, true ><<<G, 256>>>(H2, H1, H3,      B5, w1a + 1 * 2048, nullptr, nullptr, nullptr, col, vals);
        term_kernel<32, 64, 0, false, false, true ><<<G, 256>>>(H0, H2, H1,      B5, w1a + 2 * 2048, nullptr, nullptr, nullptr, col, vals);
        term_kernel<32, 64, 0, false, false, true ><<<G, 256>>>(H1, H0, H2,      B5, w1a + 3 * 2048, nullptr, nullptr, nullptr, col, vals);
        term_kernel<32, 64, 0, false, false, true ><<<G, 256>>>(H2, H1, H0,      B5, w1a + 4 * 2048, nullptr, nullptr, nullptr, col, vals);
        term_kernel<32, 64, 0, false, false, false><<<NG, 256>>>(nullptr, H2, nullptr, B5, w1a + 5 * 2048, nullptr, nullptr, nullptr, col, vals);
    }
    bnstats_kernel<<<64, 256>>>(B5, g1h, be1h, st1, 64);
    bnapply_kernel<<<(V_NODES * 64 * 4 + 255) / 256, 256>>>((__half2*)H0, (const float4*)B5, st1, 64, V_NODES * 64 * 4);
    // chebB: 64 -> 64 (+ shortcut H3@sc1 folded into k=0), in=H0, out=B4
    {
        const int NS = ns_for(64), G = NG + NS;
        term_kernel<64, 64, 32, true,  true,  true ><<<G, 256>>>(H1, H0, nullptr, B4, w1b,            b1b,    H3, sc1, col, vals);
        term_kernel<64, 64, 0,  false, false, true ><<<G, 256>>>(H2, H1, H0,      B4, w1b + 1 * 4096, nullptr, nullptr, nullptr, col, vals);
        term_kernel<64, 64, 0,  false, false, true ><<<G, 256>>>(H5, H2, H1,      B4, w1b + 2 * 4096, nullptr, nullptr, nullptr, col, vals);
        term_kernel<64, 64, 0,  false, false, true ><<<G, 256>>>(H1, H5, H2,      B4, w1b + 3 * 4096, nullptr, nullptr, nullptr, col, vals);
        term_kernel<64, 64, 0,  false, false, true ><<<G, 256>>>(H2, H1, H5,      B4, w1b + 4 * 4096, nullptr, nullptr, nullptr, col, vals);
        term_kernel<64, 64, 0,  false, false, false><<<NG, 256>>>(nullptr, H2, nullptr, B4, w1b + 5 * 4096, nullptr, nullptr, nullptr, col, vals);
    }

    // ===== Block 2 =====
    bnstats_kernel<<<64, 256>>>(B4, g2, be2, st2, 64);
    bnapply_kernel<<<(V_NODES * 64 * 4 + 255) / 256, 256>>>((__half2*)H3, (const float4*)B4, st2, 64, V_NODES * 64 * 4);
    // chebA: 64 -> 128, in=H3 (kept for shortcut), out=B5
    {
        const int NS = ns_for(64), G = NG + NS;
        term_kernel<64, 128, 0, true,  true,  true ><<<G, 256>>>(H1, H3, nullptr, B5, w2a,            b2a,    nullptr, nullptr, col, vals);
        term_kernel<64, 128, 0, false, false, true ><<<G, 256>>>(H2, H1, H3,      B5, w2a + 1 * 8192, nullptr, nullptr, nullptr, col, vals);
        term_kernel<64, 128, 0, false, false, true ><<<G, 256>>>(H0, H2, H1,      B5, w2a + 2 * 8192, nullptr, nullptr, nullptr, col, vals);
        term_kernel<64, 128, 0, false, false, true ><<<G, 256>>>(H1, H0, H2,      B5, w2a + 3 * 8192, nullptr, nullptr, nullptr, col, vals);
        term_kernel<64, 128, 0, false, false, true ><<<G, 256>>>(H2, H1, H0,      B5, w2a + 4 * 8192, nullptr, nullptr, nullptr, col, vals);
        term_kernel<64, 128, 0, false, false, false><<<NG, 256>>>(nullptr, H2, nullptr, B5, w2a + 5 * 8192, nullptr, nullptr, nullptr, col, vals);
    }
    bnstats_kernel<<<128, 256>>>(B5, g2h, be2h, st3, 128);
    bnapply_kernel<<<(V_NODES * 128 * 4 + 255) / 256, 256>>>((__half2*)H0, (const float4*)B5, st3, 128, V_NODES * 128 * 4);
    // chebB: 128 -> 128 (+ shortcut H3@sc2 folded into k=0), in=H0, out=B4
    // H5 (C=128 fp16) occupies [3.5,4.0)*BUFSZ -> disjoint from H3's C=64 use [3.0,3.25)
    {
        const int NS = ns_for(128), G = NG + NS;
        term_kernel<128, 128, 64, true,  true,  true ><<<G, 256>>>(H1, H0, nullptr, B4, w2b,             b2b,    H3, sc2, col, vals);
        term_kernel<128, 128, 0,  false, false, true ><<<G, 256>>>(H2, H1, H0,      B4, w2b + 1 * 16384, nullptr, nullptr, nullptr, col, vals);
        term_kernel<128, 128, 0,  false, false, true ><<<G, 256>>>(H5, H2, H1,      B4, w2b + 2 * 16384, nullptr, nullptr, nullptr, col, vals);
        term_kernel<128, 128, 0,  false, false, true ><<<G, 256>>>(H1, H5, H2,      B4, w2b + 3 * 16384, nullptr, nullptr, nullptr, col, vals);
        term_kernel<128, 128, 0,  false, false, true ><<<G, 256>>>(H2, H1, H5,      B4, w2b + 4 * 16384, nullptr, nullptr, nullptr, col, vals);
        term_kernel<128, 128, 0,  false, false, false><<<NG, 256>>>(nullptr, H2, nullptr, B4, w2b + 5 * 16384, nullptr, nullptr, nullptr, col, vals);
    }

    // ===== Head =====
    pool1_kernel<<<dim3(8, 25), 256>>>(pp, B4);
    head_kernel<<<1, 256>>>((float*)d_out, pp, g_out, be_out, lin_w, lin_b);
}